// round 14
// baseline (speedup 1.0000x reference)
#include <cuda_runtime.h>
#include <cuda_fp16.h>
#include <math.h>
#include <stdint.h>

// ===========================================================================
// ElectronicEmbedding (SpookyNet) — R14: pure fp16 HMMA chain, TM=32,
// 2 CTAs/SM (bubble overlap). Warp = all 32 rows x 64-col quarter.
// h kept fp32 in warp-private SMEM. Depth-4 W ring via cp.async.bulk.
// ===========================================================================

#define FDIM 256
#define TM   32
#define MAXN 200704
#define MAXB 4096
#define CHUNK 16384   // one W chunk: 2 ktiles x 32 ntiles, fp16 fragments
#define NQ 40         // total chunks (5 GEMMs x 8)
#define RING 4

__device__ __align__(16) unsigned char g_Wf[5 * 8 * CHUNK];

__device__ float g_u[FDIM];
__device__ float g_c0;
__device__ float g_cf[MAXB];
__device__ float g_ev[MAXB];
__device__ float g_anorm[MAXB];
__device__ float g_a[MAXN];
__device__ int   g_seg64;

// ---------------------------------------------------------------------------
__device__ __forceinline__ uint32_t smem_u32(const void* p) {
    uint32_t a;
    asm("{ .reg .u64 t; cvta.to.shared.u64 t, %1; cvt.u32.u64 %0, t; }"
        : "=r"(a) : "l"(p));
    return a;
}

__device__ __forceinline__ int get_seg(const void* seg, int n) {
    int b;
    if (g_seg64) b = (int)((const long long*)seg)[n];
    else         b = ((const int*)seg)[n];
    if (b < 0) b = 0;
    if (b >= MAXB) b = MAXB - 1;
    return b;
}

__device__ __forceinline__ float siluf(float x) {
    return x * (1.0f / (1.0f + __expf(-x)));
}

__device__ __forceinline__ uint32_t f16pack2(float a, float b) {
    __half2 h = __floats2half2_rn(a, b);
    return *(uint32_t*)&h;
}

// ---------------------------------------------------------------------------
// mbarrier / bulk copy
// ---------------------------------------------------------------------------
__device__ __forceinline__ void mbar_init(uint32_t m, uint32_t cnt) {
    asm volatile("mbarrier.init.shared.b64 [%0], %1;" :: "r"(m), "r"(cnt) : "memory");
}
__device__ __forceinline__ void mbar_expect(uint32_t m, uint32_t bytes) {
    asm volatile("mbarrier.arrive.expect_tx.shared.b64 _, [%0], %1;"
                 :: "r"(m), "r"(bytes) : "memory");
}
__device__ __forceinline__ void mbar_arrive(uint32_t m) {
    asm volatile("mbarrier.arrive.shared.b64 _, [%0];" :: "r"(m) : "memory");
}
__device__ __forceinline__ void mbar_wait(uint32_t m, uint32_t parity) {
    uint32_t done;
    asm volatile(
        "{\n\t.reg .pred p;\n\t"
        "mbarrier.try_wait.parity.acquire.cta.shared::cta.b64 p, [%1], %2;\n\t"
        "selp.b32 %0, 1, 0, p;\n\t}"
        : "=r"(done) : "r"(m), "r"(parity) : "memory");
    while (!done) {
        asm volatile(
            "{\n\t.reg .pred p;\n\t"
            "mbarrier.try_wait.parity.acquire.cta.shared::cta.b64 p, [%1], %2, 0x989680;\n\t"
            "selp.b32 %0, 1, 0, p;\n\t}"
            : "=r"(done) : "r"(m), "r"(parity) : "memory");
    }
}
__device__ __forceinline__ void bulk_g2s(uint32_t dst, const void* src,
                                         uint32_t bytes, uint32_t mbar) {
    asm volatile(
        "cp.async.bulk.shared::cluster.global.mbarrier::complete_tx::bytes "
        "[%0], [%1], %2, [%3];"
        :: "r"(dst), "l"(src), "r"(bytes), "r"(mbar) : "memory");
}
#define FENCE_ASYNC() asm volatile("fence.proxy.async.shared::cta;" ::: "memory")

// fp16 MMA, f32 accumulate
__device__ __forceinline__ void mma_f32(float c[4], uint4 a, uint2 b) {
    asm volatile(
        "mma.sync.aligned.m16n8k16.row.col.f32.f16.f16.f32 "
        "{%0,%1,%2,%3}, {%4,%5,%6,%7}, {%8,%9}, {%0,%1,%2,%3};"
        : "+f"(c[0]), "+f"(c[1]), "+f"(c[2]), "+f"(c[3])
        : "r"(a.x), "r"(a.y), "r"(a.z), "r"(a.w), "r"(b.x), "r"(b.y));
}

// ---------------------------------------------------------------------------
// detect / prep
// ---------------------------------------------------------------------------
__global__ void detect_kernel(const int* __restrict__ seg32, int N) {
    int last = seg32[N - 1];
    int prev = seg32[N - 2];
    g_seg64 = (last == 0 && prev > 0) ? 1 : 0;
}

__global__ void prep_kernel(const float* __restrict__ Wq,
                            const float* __restrict__ Wk,
                            const float* __restrict__ bq,
                            const float* __restrict__ E, int B) {
    int tid = threadIdx.x;
    if (blockIdx.x == 0) {
        float s = 0.0f;
#pragma unroll 8
        for (int f = 0; f < FDIM; f++)
            s = fmaf(Wk[f], Wq[f * FDIM + tid], s);
        g_u[tid] = s;
        if (tid == 0) {
            float c = 0.0f;
            for (int f = 0; f < FDIM; f++) c = fmaf(bq[f], Wk[f], c);
            g_c0 = c;
        }
    } else {
        int b = (blockIdx.x - 1) * 256 + tid;
        if (b < B) {
            float e = fabsf(E[b]);
            g_ev[b] = e;
            g_cf[b] = e / fmaxf(e, 1.0f);
            g_anorm[b] = 0.0f;
        }
    }
}

// ---------------------------------------------------------------------------
// dot: 8 rows per warp, front-batched loads (MLP 16).
// ---------------------------------------------------------------------------
__global__ void dot_kernel(const float* __restrict__ x,
                           const void* __restrict__ seg, int N) {
    __shared__ float su[FDIM];
    __shared__ float sc0;
    int tid = threadIdx.x;
    su[tid] = g_u[tid];
    if (tid == 0) sc0 = g_c0;
    __syncthreads();

    int wid = tid >> 5, lane = tid & 31;
    int n0 = (blockIdx.x * 8 + wid) * 8;
    if (n0 >= N) return;

    float4 u0 = *(const float4*)&su[4 * lane];
    float4 u1 = *(const float4*)&su[128 + 4 * lane];

    float p[8];
#pragma unroll
    for (int r = 0; r < 8; r++) {
        int n = n0 + r;
        p[r] = 0.0f;
        if (n < N) {
            const float4* xr = (const float4*)(x + (size_t)n * FDIM);
            float4 xa = xr[lane];
            float4 xb = xr[32 + lane];
            p[r] = xa.x * u0.x + xa.y * u0.y + xa.z * u0.z + xa.w * u0.w +
                   xb.x * u1.x + xb.y * u1.y + xb.z * u1.z + xb.w * u1.w;
        }
    }
#pragma unroll
    for (int r = 0; r < 8; r++)
#pragma unroll
        for (int o = 16; o > 0; o >>= 1)
            p[r] += __shfl_down_sync(0xffffffffu, p[r], o);

    if (lane == 0) {
#pragma unroll
        for (int r = 0; r < 8; r++) {
            int n = n0 + r;
            if (n < N) {
                int b = get_seg(seg, n);
                float d = (p[r] + sc0) * g_cf[b] * 0.0625f;
                float a = fmaxf(d, 0.0f) + log1pf(expf(-fabsf(d)));
                g_a[n] = a;
                atomicAdd(&g_anorm[b], a);
            }
        }
    }
}

// ---------------------------------------------------------------------------
// convW: fp32 W[out][in] -> fragment-ordered fp16 chunk images.
// chunk layout: [t2(2)][j(32)][l(32)][2 uint32] = 16KB; chunks: [m(5)][c(8)].
// ---------------------------------------------------------------------------
#define CONVW_THREADS (5 * 8 * 2 * 32 * 32)   // 81920

__global__ void convW_kernel(const float* __restrict__ Wres1,
                             const float* __restrict__ Wres2,
                             const float* __restrict__ Wout) {
    int idx = blockIdx.x * blockDim.x + threadIdx.x;
    if (idx >= CONVW_THREADS) return;
    int l  = idx & 31;
    int j  = (idx >> 5) & 31;
    int t2 = (idx >> 10) & 1;
    int c  = (idx >> 11) & 7;
    int m  = idx >> 14;
    if (m >= 5) return;

    const float* Wm;
    switch (m) {
        case 0: Wm = Wres1; break;
        case 1: Wm = Wres2; break;
        case 2: Wm = Wres1 + 65536; break;
        case 3: Wm = Wres2 + 65536; break;
        default: Wm = Wout; break;
    }
    int n  = 8 * j + (l >> 2);
    int k0 = 32 * c + 16 * t2 + (l & 3) * 2;
    const float* p = Wm + n * FDIM + k0;
    uint32_t H0 = f16pack2(p[0], p[1]);
    uint32_t H1 = f16pack2(p[8], p[9]);
    size_t base = (size_t)(m * 8 + c) * CHUNK +
                  (size_t)(((t2 * 32 + j) * 32 + l)) * 8;
    *(uint2*)(g_Wf + base) = make_uint2(H0, H1);
}

// ---------------------------------------------------------------------------
// Epilogue store helper: totals -> silu -> fp16 A frags.
// A slots: [atile a (2)][ktile (16)]; warp nh owns ktiles 4nh..4nh+3.
// ---------------------------------------------------------------------------
__device__ __forceinline__ void store_A_frags(const float Cm[2][8][4],
                                              unsigned char* aH,
                                              int nh, int l) {
#pragma unroll
    for (int a = 0; a < 2; a++) {
#pragma unroll
        for (int tt = 0; tt < 4; tt++) {
            const float* X = Cm[a][2 * tt];
            const float* Y = Cm[a][2 * tt + 1];
            uint32_t H0 = f16pack2(siluf(X[0]), siluf(X[1]));
            uint32_t H1 = f16pack2(siluf(X[2]), siluf(X[3]));
            uint32_t H2 = f16pack2(siluf(Y[0]), siluf(Y[1]));
            uint32_t H3 = f16pack2(siluf(Y[2]), siluf(Y[3]));
            int slot = a * 16 + 4 * nh + tt;
            size_t ao = (size_t)(slot * 32 + l) * 16;
            *(uint4*)(aH + ao) = make_uint4(H0, H1, H2, H3);
        }
    }
}

// ---------------------------------------------------------------------------
// chain_mma: 32 rows/CTA, 128 threads (4 warps), 2 CTAs/SM.
// warp nh owns all 32 rows x cols 64nh..64nh+63. h fp32 warp-private SMEM.
// SMEM: aH 16K | hF 32K | W ring 4x16K = 112K.
// ---------------------------------------------------------------------------
__global__ __launch_bounds__(128, 2)
void chain_mma(const void* __restrict__ seg,
               const float* __restrict__ Wv,
               float* __restrict__ out, int N) {
    extern __shared__ __align__(1024) unsigned char dyn[];
    unsigned char* aH = dyn;                    // 16 KB
    unsigned char* hF = dyn + 16384;            // 32 KB
    uint32_t wb_addr[RING];
    unsigned char* wb_ptr[RING];
#pragma unroll
    for (int i = 0; i < RING; i++) {
        wb_ptr[i] = dyn + 49152 + i * CHUNK;
        wb_addr[i] = smem_u32(wb_ptr[i]);
    }

    __shared__ __align__(8) unsigned long long s_mb[2 * RING];
    __shared__ float s_sv[TM];
    __shared__ float s_wv[FDIM];

    int tid = threadIdx.x;
    int nh = tid >> 5, l = tid & 31;
    int gid = l >> 2;
    int c2v = (l & 3) * 2;
    int r0 = blockIdx.x * TM;

    uint32_t mb_full[RING], mb_empty[RING];
#pragma unroll
    for (int i = 0; i < RING; i++) {
        mb_full[i]  = smem_u32(&s_mb[i]);
        mb_empty[i] = smem_u32(&s_mb[RING + i]);
    }

    if (tid == 0) {
#pragma unroll
        for (int i = 0; i < RING; i++) {
            mbar_init(mb_full[i], 1);
            mbar_init(mb_empty[i], 4);   // one arrive per warp
        }
        FENCE_ASYNC();
    }
    if (tid < TM) {
        int n = r0 + tid;
        float s = 0.0f;
        if (n < N) {
            int b = get_seg(seg, n);
            s = g_a[n] / (g_anorm[b] + 1e-8f) * g_ev[b];
        }
        s_sv[tid] = s;
    }
    s_wv[tid] = Wv[tid];
    s_wv[tid + 128] = Wv[tid + 128];
    __syncthreads();

    if (tid == 0) {
#pragma unroll
        for (int i = 0; i < RING; i++) {
            mbar_expect(mb_full[i], CHUNK);
            bulk_g2s(wb_addr[i], g_Wf + (size_t)i * CHUNK, CHUNK, mb_full[i]);
        }
    }

    float Cm[2][8][4];   // accumulator / current activation tile

    // warp-private h region in hF: 8 KB per warp
#define H_OFF(a, jj) ((size_t)(((nh * 16 + (a) * 8 + (jj)) * 32 + l)) * 16)

    // ---- init: h0 = s (x) Wv into Cm; hF = Cm; store A = f16(silu(h0)).
    {
#pragma unroll
        for (int a = 0; a < 2; a++) {
            int rlo = 16 * a + gid;
            float s0 = s_sv[rlo];
            float s1 = s_sv[rlo + 8];
#pragma unroll
            for (int jj = 0; jj < 8; jj++) {
                int col = 8 * (8 * nh + jj) + c2v;
                float w0 = s_wv[col], w1 = s_wv[col + 1];
                Cm[a][jj][0] = s0 * w0;
                Cm[a][jj][1] = s0 * w1;
                Cm[a][jj][2] = s1 * w0;
                Cm[a][jj][3] = s1 * w1;
                *(float4*)(hF + H_OFF(a, jj)) =
                    make_float4(Cm[a][jj][0], Cm[a][jj][1],
                                Cm[a][jj][2], Cm[a][jj][3]);
            }
        }
        store_A_frags(Cm, aH, nh, l);
    }
    __syncthreads();

#pragma unroll 1
    for (int g = 0; g < 5; g++) {
        // ---- accumulator init: residual GEMMs start from h (warp-private)
        if (g == 1 || g == 3) {
#pragma unroll
            for (int a = 0; a < 2; a++)
#pragma unroll
                for (int jj = 0; jj < 8; jj++) {
                    float4 hv = *(float4*)(hF + H_OFF(a, jj));
                    Cm[a][jj][0] = hv.x; Cm[a][jj][1] = hv.y;
                    Cm[a][jj][2] = hv.z; Cm[a][jj][3] = hv.w;
                }
        } else {
#pragma unroll
            for (int a = 0; a < 2; a++)
#pragma unroll
                for (int jj = 0; jj < 8; jj++)
                    Cm[a][jj][0] = Cm[a][jj][1] = Cm[a][jj][2] = Cm[a][jj][3] = 0.0f;
        }

        // ---- mainloop: 8 k-chunks of 32
#pragma unroll 1
        for (int c = 0; c < 8; c++) {
            int q = 8 * g + c;
            int s = q & (RING - 1);
            mbar_wait(mb_full[s], (uint32_t)((q >> 2) & 1));
            const unsigned char* wt = wb_ptr[s] + (size_t)l * 8 + nh * 2048;

#pragma unroll
            for (int t = 0; t < 2; t++) {
                int slot0 = 0 * 16 + 2 * c + t;
                int slot1 = 1 * 16 + 2 * c + t;
                uint4 ah0 = *(const uint4*)(aH + (size_t)(slot0 * 32 + l) * 16);
                uint4 ah1 = *(const uint4*)(aH + (size_t)(slot1 * 32 + l) * 16);
                const unsigned char* wtt = wt + t * 8192;
#pragma unroll
                for (int jj = 0; jj < 8; jj++) {
                    uint2 bh = *(const uint2*)(wtt + jj * 256);
                    mma_f32(Cm[0][jj], ah0, bh);
                    mma_f32(Cm[1][jj], ah1, bh);
                }
            }
            if (l == 0) mbar_arrive(mb_empty[s]);
            if (tid == 0 && q + RING < NQ) {
                int qq = q + RING;
                int fs = qq & (RING - 1);
                mbar_wait(mb_empty[fs], (uint32_t)(((qq >> 2) + 1) & 1));
                mbar_expect(mb_full[fs], CHUNK);
                bulk_g2s(wb_addr[fs], g_Wf + (size_t)qq * CHUNK, CHUNK,
                         mb_full[fs]);
            }
        }

        __syncthreads();   // all warps done reading A

        // ---- epilogue
        if (g == 4) {
#pragma unroll
            for (int a = 0; a < 2; a++) {
                int rlo = r0 + 16 * a + gid;
#pragma unroll
                for (int jj = 0; jj < 8; jj++) {
                    int col = 8 * (8 * nh + jj) + c2v;
                    if (rlo < N)
                        *(float2*)(out + (size_t)rlo * FDIM + col) =
                            make_float2(Cm[a][jj][0], Cm[a][jj][1]);
                    if (rlo + 8 < N)
                        *(float2*)(out + (size_t)(rlo + 8) * FDIM + col) =
                            make_float2(Cm[a][jj][2], Cm[a][jj][3]);
                }
            }
        } else {
            if (g == 1 || g == 3) {   // h updated: hF = Cm (warp-private)
#pragma unroll
                for (int a = 0; a < 2; a++)
#pragma unroll
                    for (int jj = 0; jj < 8; jj++)
                        *(float4*)(hF + H_OFF(a, jj)) =
                            make_float4(Cm[a][jj][0], Cm[a][jj][1],
                                        Cm[a][jj][2], Cm[a][jj][3]);
            }
            store_A_frags(Cm, aH, nh, l);
            __syncthreads();   // publish A before next GEMM reads
        }
    }
#undef H_OFF
}

// ---------------------------------------------------------------------------
extern "C" void kernel_launch(void* const* d_in, const int* in_sizes, int n_in,
                              void* d_out, int out_size) {
    int base = (n_in >= 11 && in_sizes[2] == 1) ? 1 : 0;

    const float* x     = (const float*)d_in[0];
    const float* E     = (const float*)d_in[1];
    const void*  seg   = d_in[2 + base];
    const float* Wq    = (const float*)d_in[3 + base];
    const float* bq    = (const float*)d_in[4 + base];
    const float* Wk    = (const float*)d_in[5 + base];
    const float* Wv    = (const float*)d_in[6 + base];
    const float* Wres1 = (const float*)d_in[7 + base];
    const float* Wres2 = (const float*)d_in[8 + base];
    const float* Wout  = (const float*)d_in[9 + base];

    int N = in_sizes[0] / FDIM;
    int B = in_sizes[1];
    if (N > MAXN) N = MAXN;
    if (B > MAXB) B = MAXB;

    detect_kernel<<<1, 1>>>((const int*)seg, N);
    prep_kernel<<<1 + (B + 255) / 256, 256>>>(Wq, Wk, bq, E, B);
    convW_kernel<<<(CONVW_THREADS + 127) / 128, 128>>>(Wres1, Wres2, Wout);
    dot_kernel<<<(N + 63) / 64, 256>>>(x, seg, N);

    int smem_bytes = 16384 + 32768 + RING * CHUNK;   // 112 KB
    cudaFuncSetAttribute(chain_mma, cudaFuncAttributeMaxDynamicSharedMemorySize,
                         smem_bytes);
    chain_mma<<<(N + TM - 1) / TM, 128, smem_bytes>>>(seg, Wv, (float*)d_out, N);
}

// round 15
// speedup vs baseline: 1.7567x; 1.7567x over previous
#include <cuda_runtime.h>
#include <cuda_fp16.h>
#include <math.h>
#include <stdint.h>

// ===========================================================================
// ElectronicEmbedding (SpookyNet) — R15: pure fp16 HMMA chain, TM=32,
// TRUE 2 CTAs/SM: h in registers, smem = 80 KB/CTA (aH 16K + ring 64K).
// Warp = all 32 rows x 64-col quarter. Depth-4 W ring via cp.async.bulk.
// ===========================================================================

#define FDIM 256
#define TM   32
#define MAXN 200704
#define MAXB 4096
#define CHUNK 16384   // one W chunk: 2 ktiles x 32 ntiles, fp16 fragments
#define NQ 40         // total chunks (5 GEMMs x 8)
#define RING 4

__device__ __align__(16) unsigned char g_Wf[5 * 8 * CHUNK];

__device__ float g_u[FDIM];
__device__ float g_c0;
__device__ float g_cf[MAXB];
__device__ float g_ev[MAXB];
__device__ float g_anorm[MAXB];
__device__ float g_a[MAXN];
__device__ int   g_seg64;

// ---------------------------------------------------------------------------
__device__ __forceinline__ uint32_t smem_u32(const void* p) {
    uint32_t a;
    asm("{ .reg .u64 t; cvta.to.shared.u64 t, %1; cvt.u32.u64 %0, t; }"
        : "=r"(a) : "l"(p));
    return a;
}

__device__ __forceinline__ int get_seg(const void* seg, int n) {
    int b;
    if (g_seg64) b = (int)((const long long*)seg)[n];
    else         b = ((const int*)seg)[n];
    if (b < 0) b = 0;
    if (b >= MAXB) b = MAXB - 1;
    return b;
}

__device__ __forceinline__ float siluf(float x) {
    return x * (1.0f / (1.0f + __expf(-x)));
}

__device__ __forceinline__ uint32_t f16pack2(float a, float b) {
    __half2 h = __floats2half2_rn(a, b);
    return *(uint32_t*)&h;
}

// ---------------------------------------------------------------------------
// mbarrier / bulk copy
// ---------------------------------------------------------------------------
__device__ __forceinline__ void mbar_init(uint32_t m, uint32_t cnt) {
    asm volatile("mbarrier.init.shared.b64 [%0], %1;" :: "r"(m), "r"(cnt) : "memory");
}
__device__ __forceinline__ void mbar_expect(uint32_t m, uint32_t bytes) {
    asm volatile("mbarrier.arrive.expect_tx.shared.b64 _, [%0], %1;"
                 :: "r"(m), "r"(bytes) : "memory");
}
__device__ __forceinline__ void mbar_arrive(uint32_t m) {
    asm volatile("mbarrier.arrive.shared.b64 _, [%0];" :: "r"(m) : "memory");
}
__device__ __forceinline__ void mbar_wait(uint32_t m, uint32_t parity) {
    uint32_t done;
    asm volatile(
        "{\n\t.reg .pred p;\n\t"
        "mbarrier.try_wait.parity.acquire.cta.shared::cta.b64 p, [%1], %2;\n\t"
        "selp.b32 %0, 1, 0, p;\n\t}"
        : "=r"(done) : "r"(m), "r"(parity) : "memory");
    while (!done) {
        asm volatile(
            "{\n\t.reg .pred p;\n\t"
            "mbarrier.try_wait.parity.acquire.cta.shared::cta.b64 p, [%1], %2, 0x989680;\n\t"
            "selp.b32 %0, 1, 0, p;\n\t}"
            : "=r"(done) : "r"(m), "r"(parity) : "memory");
    }
}
__device__ __forceinline__ void bulk_g2s(uint32_t dst, const void* src,
                                         uint32_t bytes, uint32_t mbar) {
    asm volatile(
        "cp.async.bulk.shared::cluster.global.mbarrier::complete_tx::bytes "
        "[%0], [%1], %2, [%3];"
        :: "r"(dst), "l"(src), "r"(bytes), "r"(mbar) : "memory");
}
#define FENCE_ASYNC() asm volatile("fence.proxy.async.shared::cta;" ::: "memory")

// fp16 MMA, f32 accumulate
__device__ __forceinline__ void mma_f32(float c[4], uint4 a, uint2 b) {
    asm volatile(
        "mma.sync.aligned.m16n8k16.row.col.f32.f16.f16.f32 "
        "{%0,%1,%2,%3}, {%4,%5,%6,%7}, {%8,%9}, {%0,%1,%2,%3};"
        : "+f"(c[0]), "+f"(c[1]), "+f"(c[2]), "+f"(c[3])
        : "r"(a.x), "r"(a.y), "r"(a.z), "r"(a.w), "r"(b.x), "r"(b.y));
}

// ---------------------------------------------------------------------------
// detect / prep
// ---------------------------------------------------------------------------
__global__ void detect_kernel(const int* __restrict__ seg32, int N) {
    int last = seg32[N - 1];
    int prev = seg32[N - 2];
    g_seg64 = (last == 0 && prev > 0) ? 1 : 0;
}

__global__ void prep_kernel(const float* __restrict__ Wq,
                            const float* __restrict__ Wk,
                            const float* __restrict__ bq,
                            const float* __restrict__ E, int B) {
    int tid = threadIdx.x;
    if (blockIdx.x == 0) {
        float s = 0.0f;
#pragma unroll 8
        for (int f = 0; f < FDIM; f++)
            s = fmaf(Wk[f], Wq[f * FDIM + tid], s);
        g_u[tid] = s;
        if (tid == 0) {
            float c = 0.0f;
            for (int f = 0; f < FDIM; f++) c = fmaf(bq[f], Wk[f], c);
            g_c0 = c;
        }
    } else {
        int b = (blockIdx.x - 1) * 256 + tid;
        if (b < B) {
            float e = fabsf(E[b]);
            g_ev[b] = e;
            g_cf[b] = e / fmaxf(e, 1.0f);
            g_anorm[b] = 0.0f;
        }
    }
}

// ---------------------------------------------------------------------------
// dot: 8 rows per warp, front-batched loads (MLP 16).
// ---------------------------------------------------------------------------
__global__ void dot_kernel(const float* __restrict__ x,
                           const void* __restrict__ seg, int N) {
    __shared__ float su[FDIM];
    __shared__ float sc0;
    int tid = threadIdx.x;
    su[tid] = g_u[tid];
    if (tid == 0) sc0 = g_c0;
    __syncthreads();

    int wid = tid >> 5, lane = tid & 31;
    int n0 = (blockIdx.x * 8 + wid) * 8;
    if (n0 >= N) return;

    float4 u0 = *(const float4*)&su[4 * lane];
    float4 u1 = *(const float4*)&su[128 + 4 * lane];

    float p[8];
#pragma unroll
    for (int r = 0; r < 8; r++) {
        int n = n0 + r;
        p[r] = 0.0f;
        if (n < N) {
            const float4* xr = (const float4*)(x + (size_t)n * FDIM);
            float4 xa = xr[lane];
            float4 xb = xr[32 + lane];
            p[r] = xa.x * u0.x + xa.y * u0.y + xa.z * u0.z + xa.w * u0.w +
                   xb.x * u1.x + xb.y * u1.y + xb.z * u1.z + xb.w * u1.w;
        }
    }
#pragma unroll
    for (int r = 0; r < 8; r++)
#pragma unroll
        for (int o = 16; o > 0; o >>= 1)
            p[r] += __shfl_down_sync(0xffffffffu, p[r], o);

    if (lane == 0) {
#pragma unroll
        for (int r = 0; r < 8; r++) {
            int n = n0 + r;
            if (n < N) {
                int b = get_seg(seg, n);
                float d = (p[r] + sc0) * g_cf[b] * 0.0625f;
                float a = fmaxf(d, 0.0f) + log1pf(expf(-fabsf(d)));
                g_a[n] = a;
                atomicAdd(&g_anorm[b], a);
            }
        }
    }
}

// ---------------------------------------------------------------------------
// convW: fp32 W[out][in] -> fragment-ordered fp16 chunk images.
// chunk layout: [t2(2)][j(32)][l(32)][2 uint32] = 16KB; chunks: [m(5)][c(8)].
// ---------------------------------------------------------------------------
#define CONVW_THREADS (5 * 8 * 2 * 32 * 32)   // 81920

__global__ void convW_kernel(const float* __restrict__ Wres1,
                             const float* __restrict__ Wres2,
                             const float* __restrict__ Wout) {
    int idx = blockIdx.x * blockDim.x + threadIdx.x;
    if (idx >= CONVW_THREADS) return;
    int l  = idx & 31;
    int j  = (idx >> 5) & 31;
    int t2 = (idx >> 10) & 1;
    int c  = (idx >> 11) & 7;
    int m  = idx >> 14;
    if (m >= 5) return;

    const float* Wm;
    switch (m) {
        case 0: Wm = Wres1; break;
        case 1: Wm = Wres2; break;
        case 2: Wm = Wres1 + 65536; break;
        case 3: Wm = Wres2 + 65536; break;
        default: Wm = Wout; break;
    }
    int n  = 8 * j + (l >> 2);
    int k0 = 32 * c + 16 * t2 + (l & 3) * 2;
    const float* p = Wm + n * FDIM + k0;
    uint32_t H0 = f16pack2(p[0], p[1]);
    uint32_t H1 = f16pack2(p[8], p[9]);
    size_t base = (size_t)(m * 8 + c) * CHUNK +
                  (size_t)(((t2 * 32 + j) * 32 + l)) * 8;
    *(uint2*)(g_Wf + base) = make_uint2(H0, H1);
}

// ---------------------------------------------------------------------------
// Epilogue store helper: totals -> silu -> fp16 A frags.
// A slots: [atile a (2)][ktile (16)]; warp nh owns ktiles 4nh..4nh+3.
// ---------------------------------------------------------------------------
__device__ __forceinline__ void store_A_frags(const float Cm[2][8][4],
                                              unsigned char* aH,
                                              int nh, int l) {
#pragma unroll
    for (int a = 0; a < 2; a++) {
#pragma unroll
        for (int tt = 0; tt < 4; tt++) {
            const float* X = Cm[a][2 * tt];
            const float* Y = Cm[a][2 * tt + 1];
            uint32_t H0 = f16pack2(siluf(X[0]), siluf(X[1]));
            uint32_t H1 = f16pack2(siluf(X[2]), siluf(X[3]));
            uint32_t H2 = f16pack2(siluf(Y[0]), siluf(Y[1]));
            uint32_t H3 = f16pack2(siluf(Y[2]), siluf(Y[3]));
            int slot = a * 16 + 4 * nh + tt;
            size_t ao = (size_t)(slot * 32 + l) * 16;
            *(uint4*)(aH + ao) = make_uint4(H0, H1, H2, H3);
        }
    }
}

// ---------------------------------------------------------------------------
// chain_mma: 32 rows/CTA, 128 threads (4 warps), 2 CTAs/SM (real this time).
// warp nh owns all 32 rows x cols 64nh..64nh+63. h in registers.
// SMEM: aH 16K | W ring 4x16K = 80K per CTA.
// ---------------------------------------------------------------------------
__global__ __launch_bounds__(128, 2)
void chain_mma(const void* __restrict__ seg,
               const float* __restrict__ Wv,
               float* __restrict__ out, int N) {
    extern __shared__ __align__(1024) unsigned char dyn[];
    unsigned char* aH = dyn;                    // 16 KB
    uint32_t wb_addr[RING];
    unsigned char* wb_ptr[RING];
#pragma unroll
    for (int i = 0; i < RING; i++) {
        wb_ptr[i] = dyn + 16384 + i * CHUNK;
        wb_addr[i] = smem_u32(wb_ptr[i]);
    }

    __shared__ __align__(8) unsigned long long s_mb[2 * RING];
    __shared__ float s_sv[TM];
    __shared__ float s_wv[FDIM];

    int tid = threadIdx.x;
    int nh = tid >> 5, l = tid & 31;
    int gid = l >> 2;
    int c2v = (l & 3) * 2;
    int r0 = blockIdx.x * TM;

    uint32_t mb_full[RING], mb_empty[RING];
#pragma unroll
    for (int i = 0; i < RING; i++) {
        mb_full[i]  = smem_u32(&s_mb[i]);
        mb_empty[i] = smem_u32(&s_mb[RING + i]);
    }

    if (tid == 0) {
#pragma unroll
        for (int i = 0; i < RING; i++) {
            mbar_init(mb_full[i], 1);
            mbar_init(mb_empty[i], 4);   // one arrive per warp
        }
        FENCE_ASYNC();
    }
    if (tid < TM) {
        int n = r0 + tid;
        float s = 0.0f;
        if (n < N) {
            int b = get_seg(seg, n);
            s = g_a[n] / (g_anorm[b] + 1e-8f) * g_ev[b];
        }
        s_sv[tid] = s;
    }
    s_wv[tid] = Wv[tid];
    s_wv[tid + 128] = Wv[tid + 128];
    __syncthreads();

    if (tid == 0) {
#pragma unroll
        for (int i = 0; i < RING; i++) {
            mbar_expect(mb_full[i], CHUNK);
            bulk_g2s(wb_addr[i], g_Wf + (size_t)i * CHUNK, CHUNK, mb_full[i]);
        }
    }

    float Cm[2][8][4];   // accumulator / current activation tile
    float hR[2][8][4];   // residual h (register-resident)

    // ---- init: h0 = s (x) Wv into Cm; hR = Cm; store A = f16(silu(h0)).
    {
#pragma unroll
        for (int a = 0; a < 2; a++) {
            int rlo = 16 * a + gid;
            float s0 = s_sv[rlo];
            float s1 = s_sv[rlo + 8];
#pragma unroll
            for (int jj = 0; jj < 8; jj++) {
                int col = 8 * (8 * nh + jj) + c2v;
                float w0 = s_wv[col], w1 = s_wv[col + 1];
                Cm[a][jj][0] = s0 * w0;
                Cm[a][jj][1] = s0 * w1;
                Cm[a][jj][2] = s1 * w0;
                Cm[a][jj][3] = s1 * w1;
                hR[a][jj][0] = Cm[a][jj][0];
                hR[a][jj][1] = Cm[a][jj][1];
                hR[a][jj][2] = Cm[a][jj][2];
                hR[a][jj][3] = Cm[a][jj][3];
            }
        }
        store_A_frags(Cm, aH, nh, l);
    }
    __syncthreads();

#pragma unroll 1
    for (int g = 0; g < 5; g++) {
        // ---- accumulator init: residual GEMMs start from h
        if (g == 1 || g == 3) {
#pragma unroll
            for (int a = 0; a < 2; a++)
#pragma unroll
                for (int jj = 0; jj < 8; jj++) {
                    Cm[a][jj][0] = hR[a][jj][0];
                    Cm[a][jj][1] = hR[a][jj][1];
                    Cm[a][jj][2] = hR[a][jj][2];
                    Cm[a][jj][3] = hR[a][jj][3];
                }
        } else {
#pragma unroll
            for (int a = 0; a < 2; a++)
#pragma unroll
                for (int jj = 0; jj < 8; jj++)
                    Cm[a][jj][0] = Cm[a][jj][1] = Cm[a][jj][2] = Cm[a][jj][3] = 0.0f;
        }

        // ---- mainloop: 8 k-chunks of 32
#pragma unroll 1
        for (int c = 0; c < 8; c++) {
            int q = 8 * g + c;
            int s = q & (RING - 1);
            mbar_wait(mb_full[s], (uint32_t)((q >> 2) & 1));
            const unsigned char* wt = wb_ptr[s] + (size_t)l * 8 + nh * 2048;

#pragma unroll
            for (int t = 0; t < 2; t++) {
                int slot0 = 0 * 16 + 2 * c + t;
                int slot1 = 1 * 16 + 2 * c + t;
                uint4 ah0 = *(const uint4*)(aH + (size_t)(slot0 * 32 + l) * 16);
                uint4 ah1 = *(const uint4*)(aH + (size_t)(slot1 * 32 + l) * 16);
                const unsigned char* wtt = wt + t * 8192;
#pragma unroll
                for (int jj = 0; jj < 8; jj++) {
                    uint2 bh = *(const uint2*)(wtt + jj * 256);
                    mma_f32(Cm[0][jj], ah0, bh);
                    mma_f32(Cm[1][jj], ah1, bh);
                }
            }
            if (l == 0) mbar_arrive(mb_empty[s]);
            if (tid == 0 && q + RING < NQ) {
                int qq = q + RING;
                int fs = qq & (RING - 1);
                mbar_wait(mb_empty[fs], (uint32_t)(((qq >> 2) + 1) & 1));
                mbar_expect(mb_full[fs], CHUNK);
                bulk_g2s(wb_addr[fs], g_Wf + (size_t)qq * CHUNK, CHUNK,
                         mb_full[fs]);
            }
        }

        __syncthreads();   // all warps done reading A

        // ---- epilogue
        if (g == 4) {
#pragma unroll
            for (int a = 0; a < 2; a++) {
                int rlo = r0 + 16 * a + gid;
#pragma unroll
                for (int jj = 0; jj < 8; jj++) {
                    int col = 8 * (8 * nh + jj) + c2v;
                    if (rlo < N)
                        *(float2*)(out + (size_t)rlo * FDIM + col) =
                            make_float2(Cm[a][jj][0], Cm[a][jj][1]);
                    if (rlo + 8 < N)
                        *(float2*)(out + (size_t)(rlo + 8) * FDIM + col) =
                            make_float2(Cm[a][jj][2], Cm[a][jj][3]);
                }
            }
        } else {
            if (g == 1 || g == 3) {   // h updated: hR = Cm
#pragma unroll
                for (int a = 0; a < 2; a++)
#pragma unroll
                    for (int jj = 0; jj < 8; jj++) {
                        hR[a][jj][0] = Cm[a][jj][0];
                        hR[a][jj][1] = Cm[a][jj][1];
                        hR[a][jj][2] = Cm[a][jj][2];
                        hR[a][jj][3] = Cm[a][jj][3];
                    }
            }
            store_A_frags(Cm, aH, nh, l);
            __syncthreads();   // publish A before next GEMM reads
        }
    }
}

// ---------------------------------------------------------------------------
extern "C" void kernel_launch(void* const* d_in, const int* in_sizes, int n_in,
                              void* d_out, int out_size) {
    int base = (n_in >= 11 && in_sizes[2] == 1) ? 1 : 0;

    const float* x     = (const float*)d_in[0];
    const float* E     = (const float*)d_in[1];
    const void*  seg   = d_in[2 + base];
    const float* Wq    = (const float*)d_in[3 + base];
    const float* bq    = (const float*)d_in[4 + base];
    const float* Wk    = (const float*)d_in[5 + base];
    const float* Wv    = (const float*)d_in[6 + base];
    const float* Wres1 = (const float*)d_in[7 + base];
    const float* Wres2 = (const float*)d_in[8 + base];
    const float* Wout  = (const float*)d_in[9 + base];

    int N = in_sizes[0] / FDIM;
    int B = in_sizes[1];
    if (N > MAXN) N = MAXN;
    if (B > MAXB) B = MAXB;

    detect_kernel<<<1, 1>>>((const int*)seg, N);
    prep_kernel<<<1 + (B + 255) / 256, 256>>>(Wq, Wk, bq, E, B);
    convW_kernel<<<(CONVW_THREADS + 127) / 128, 128>>>(Wres1, Wres2, Wout);
    dot_kernel<<<(N + 63) / 64, 256>>>(x, seg, N);

    int smem_bytes = 16384 + RING * CHUNK;   // 80 KB per CTA
    cudaFuncSetAttribute(chain_mma, cudaFuncAttributeMaxDynamicSharedMemorySize,
                         smem_bytes);
    chain_mma<<<(N + TM - 1) / TM, 128, smem_bytes>>>(seg, Wv, (float*)d_out, N);
}

// round 16
// speedup vs baseline: 1.8764x; 1.0682x over previous
#include <cuda_runtime.h>
#include <cuda_fp16.h>
#include <math.h>
#include <stdint.h>

// ===========================================================================
// ElectronicEmbedding (SpookyNet) — R16: pure fp16 HMMA chain, TM=64,
// 64KB W superchunks (4 k-chunks per mbar wait), RING=2, h in registers.
// Warp = (m = w>>2 rows-half, nh = w&3 col-quarter): 32 rows x 64 cols.
// ===========================================================================

#define FDIM 256
#define TM   64
#define MAXN 200704
#define MAXB 4096
#define KCH  16384            // one k-chunk W image (2 ktiles x 32 ntiles)
#define SCHUNK (4 * KCH)      // 64KB superchunk = 4 k-chunks
#define NSUPER 10             // 5 GEMMs x 2 superchunks
#define RING 2

__device__ __align__(16) unsigned char g_Wf[5 * 8 * KCH];

__device__ float g_u[FDIM];
__device__ float g_c0;
__device__ float g_cf[MAXB];
__device__ float g_ev[MAXB];
__device__ float g_anorm[MAXB];
__device__ float g_a[MAXN];
__device__ int   g_seg64;

// ---------------------------------------------------------------------------
__device__ __forceinline__ uint32_t smem_u32(const void* p) {
    uint32_t a;
    asm("{ .reg .u64 t; cvta.to.shared.u64 t, %1; cvt.u32.u64 %0, t; }"
        : "=r"(a) : "l"(p));
    return a;
}

__device__ __forceinline__ int get_seg(const void* seg, int n) {
    int b;
    if (g_seg64) b = (int)((const long long*)seg)[n];
    else         b = ((const int*)seg)[n];
    if (b < 0) b = 0;
    if (b >= MAXB) b = MAXB - 1;
    return b;
}

__device__ __forceinline__ float siluf(float x) {
    return x * (1.0f / (1.0f + __expf(-x)));
}

__device__ __forceinline__ uint32_t f16pack2(float a, float b) {
    __half2 h = __floats2half2_rn(a, b);
    return *(uint32_t*)&h;
}

// ---------------------------------------------------------------------------
// mbarrier / bulk copy
// ---------------------------------------------------------------------------
__device__ __forceinline__ void mbar_init(uint32_t m, uint32_t cnt) {
    asm volatile("mbarrier.init.shared.b64 [%0], %1;" :: "r"(m), "r"(cnt) : "memory");
}
__device__ __forceinline__ void mbar_expect(uint32_t m, uint32_t bytes) {
    asm volatile("mbarrier.arrive.expect_tx.shared.b64 _, [%0], %1;"
                 :: "r"(m), "r"(bytes) : "memory");
}
__device__ __forceinline__ void mbar_arrive(uint32_t m) {
    asm volatile("mbarrier.arrive.shared.b64 _, [%0];" :: "r"(m) : "memory");
}
__device__ __forceinline__ void mbar_wait(uint32_t m, uint32_t parity) {
    uint32_t done;
    asm volatile(
        "{\n\t.reg .pred p;\n\t"
        "mbarrier.try_wait.parity.acquire.cta.shared::cta.b64 p, [%1], %2;\n\t"
        "selp.b32 %0, 1, 0, p;\n\t}"
        : "=r"(done) : "r"(m), "r"(parity) : "memory");
    while (!done) {
        asm volatile(
            "{\n\t.reg .pred p;\n\t"
            "mbarrier.try_wait.parity.acquire.cta.shared::cta.b64 p, [%1], %2, 0x989680;\n\t"
            "selp.b32 %0, 1, 0, p;\n\t}"
            : "=r"(done) : "r"(m), "r"(parity) : "memory");
    }
}
__device__ __forceinline__ void bulk_g2s(uint32_t dst, const void* src,
                                         uint32_t bytes, uint32_t mbar) {
    asm volatile(
        "cp.async.bulk.shared::cluster.global.mbarrier::complete_tx::bytes "
        "[%0], [%1], %2, [%3];"
        :: "r"(dst), "l"(src), "r"(bytes), "r"(mbar) : "memory");
}
#define FENCE_ASYNC() asm volatile("fence.proxy.async.shared::cta;" ::: "memory")

// fp16 MMA, f32 accumulate
__device__ __forceinline__ void mma_f32(float c[4], uint4 a, uint2 b) {
    asm volatile(
        "mma.sync.aligned.m16n8k16.row.col.f32.f16.f16.f32 "
        "{%0,%1,%2,%3}, {%4,%5,%6,%7}, {%8,%9}, {%0,%1,%2,%3};"
        : "+f"(c[0]), "+f"(c[1]), "+f"(c[2]), "+f"(c[3])
        : "r"(a.x), "r"(a.y), "r"(a.z), "r"(a.w), "r"(b.x), "r"(b.y));
}

// ---------------------------------------------------------------------------
// detect / prep
// ---------------------------------------------------------------------------
__global__ void detect_kernel(const int* __restrict__ seg32, int N) {
    int last = seg32[N - 1];
    int prev = seg32[N - 2];
    g_seg64 = (last == 0 && prev > 0) ? 1 : 0;
}

__global__ void prep_kernel(const float* __restrict__ Wq,
                            const float* __restrict__ Wk,
                            const float* __restrict__ bq,
                            const float* __restrict__ E, int B) {
    int tid = threadIdx.x;
    if (blockIdx.x == 0) {
        float s = 0.0f;
#pragma unroll 8
        for (int f = 0; f < FDIM; f++)
            s = fmaf(Wk[f], Wq[f * FDIM + tid], s);
        g_u[tid] = s;
        if (tid == 0) {
            float c = 0.0f;
            for (int f = 0; f < FDIM; f++) c = fmaf(bq[f], Wk[f], c);
            g_c0 = c;
        }
    } else {
        int b = (blockIdx.x - 1) * 256 + tid;
        if (b < B) {
            float e = fabsf(E[b]);
            g_ev[b] = e;
            g_cf[b] = e / fmaxf(e, 1.0f);
            g_anorm[b] = 0.0f;
        }
    }
}

// ---------------------------------------------------------------------------
// dot: 8 rows per warp, front-batched loads (MLP 16).
// ---------------------------------------------------------------------------
__global__ void dot_kernel(const float* __restrict__ x,
                           const void* __restrict__ seg, int N) {
    __shared__ float su[FDIM];
    __shared__ float sc0;
    int tid = threadIdx.x;
    su[tid] = g_u[tid];
    if (tid == 0) sc0 = g_c0;
    __syncthreads();

    int wid = tid >> 5, lane = tid & 31;
    int n0 = (blockIdx.x * 8 + wid) * 8;
    if (n0 >= N) return;

    float4 u0 = *(const float4*)&su[4 * lane];
    float4 u1 = *(const float4*)&su[128 + 4 * lane];

    float p[8];
#pragma unroll
    for (int r = 0; r < 8; r++) {
        int n = n0 + r;
        p[r] = 0.0f;
        if (n < N) {
            const float4* xr = (const float4*)(x + (size_t)n * FDIM);
            float4 xa = xr[lane];
            float4 xb = xr[32 + lane];
            p[r] = xa.x * u0.x + xa.y * u0.y + xa.z * u0.z + xa.w * u0.w +
                   xb.x * u1.x + xb.y * u1.y + xb.z * u1.z + xb.w * u1.w;
        }
    }
#pragma unroll
    for (int r = 0; r < 8; r++)
#pragma unroll
        for (int o = 16; o > 0; o >>= 1)
            p[r] += __shfl_down_sync(0xffffffffu, p[r], o);

    if (lane == 0) {
#pragma unroll
        for (int r = 0; r < 8; r++) {
            int n = n0 + r;
            if (n < N) {
                int b = get_seg(seg, n);
                float d = (p[r] + sc0) * g_cf[b] * 0.0625f;
                float a = fmaxf(d, 0.0f) + log1pf(expf(-fabsf(d)));
                g_a[n] = a;
                atomicAdd(&g_anorm[b], a);
            }
        }
    }
}

// ---------------------------------------------------------------------------
// convW: fp32 W[out][in] -> fragment-ordered fp16 chunk images.
// chunk layout: [t2(2)][j(32)][l(32)][2 uint32] = 16KB; chunks: [m(5)][c(8)].
// (Contiguous per GEMM, so a 64KB superchunk = 4 consecutive chunk images.)
// ---------------------------------------------------------------------------
#define CONVW_THREADS (5 * 8 * 2 * 32 * 32)   // 81920

__global__ void convW_kernel(const float* __restrict__ Wres1,
                             const float* __restrict__ Wres2,
                             const float* __restrict__ Wout) {
    int idx = blockIdx.x * blockDim.x + threadIdx.x;
    if (idx >= CONVW_THREADS) return;
    int l  = idx & 31;
    int j  = (idx >> 5) & 31;
    int t2 = (idx >> 10) & 1;
    int c  = (idx >> 11) & 7;
    int m  = idx >> 14;
    if (m >= 5) return;

    const float* Wm;
    switch (m) {
        case 0: Wm = Wres1; break;
        case 1: Wm = Wres2; break;
        case 2: Wm = Wres1 + 65536; break;
        case 3: Wm = Wres2 + 65536; break;
        default: Wm = Wout; break;
    }
    int n  = 8 * j + (l >> 2);
    int k0 = 32 * c + 16 * t2 + (l & 3) * 2;
    const float* p = Wm + n * FDIM + k0;
    uint32_t H0 = f16pack2(p[0], p[1]);
    uint32_t H1 = f16pack2(p[8], p[9]);
    size_t base = (size_t)(m * 8 + c) * KCH +
                  (size_t)(((t2 * 32 + j) * 32 + l)) * 8;
    *(uint2*)(g_Wf + base) = make_uint2(H0, H1);
}

// ---------------------------------------------------------------------------
// Epilogue store helper: totals -> silu -> fp16 A frags.
// A slots: [atile (4)][ktile (16)]; warp (m,nh) owns atiles 2m,2m+1,
// ktiles 4nh..4nh+3.
// ---------------------------------------------------------------------------
__device__ __forceinline__ void store_A_frags(const float Cm[2][8][4],
                                              unsigned char* aH,
                                              int m, int nh, int l) {
#pragma unroll
    for (int a = 0; a < 2; a++) {
#pragma unroll
        for (int tt = 0; tt < 4; tt++) {
            const float* X = Cm[a][2 * tt];
            const float* Y = Cm[a][2 * tt + 1];
            uint32_t H0 = f16pack2(siluf(X[0]), siluf(X[1]));
            uint32_t H1 = f16pack2(siluf(X[2]), siluf(X[3]));
            uint32_t H2 = f16pack2(siluf(Y[0]), siluf(Y[1]));
            uint32_t H3 = f16pack2(siluf(Y[2]), siluf(Y[3]));
            int slot = (2 * m + a) * 16 + 4 * nh + tt;
            size_t ao = (size_t)(slot * 32 + l) * 16;
            *(uint4*)(aH + ao) = make_uint4(H0, H1, H2, H3);
        }
    }
}

// ---------------------------------------------------------------------------
// chain_mma: 64 rows/CTA, 256 threads (8 warps), 1 CTA/SM.
// SMEM: aH 32K | W ring 2 x 64K = 160K.
// ---------------------------------------------------------------------------
__global__ __launch_bounds__(256, 1)
void chain_mma(const void* __restrict__ seg,
               const float* __restrict__ Wv,
               float* __restrict__ out, int N) {
    extern __shared__ __align__(1024) unsigned char dyn[];
    unsigned char* aH = dyn;                    // 32 KB
    uint32_t wb_addr[RING];
    unsigned char* wb_ptr[RING];
#pragma unroll
    for (int i = 0; i < RING; i++) {
        wb_ptr[i] = dyn + 32768 + i * SCHUNK;
        wb_addr[i] = smem_u32(wb_ptr[i]);
    }

    __shared__ __align__(8) unsigned long long s_mb[2 * RING];
    __shared__ float s_sv[TM];
    __shared__ float s_wv[FDIM];

    int tid = threadIdx.x;
    int w = tid >> 5, l = tid & 31;
    int m = w >> 2, nh = w & 3;
    int gid = l >> 2;
    int c2v = (l & 3) * 2;
    int r0 = blockIdx.x * TM;

    uint32_t mb_full[RING], mb_empty[RING];
#pragma unroll
    for (int i = 0; i < RING; i++) {
        mb_full[i]  = smem_u32(&s_mb[i]);
        mb_empty[i] = smem_u32(&s_mb[RING + i]);
    }

    if (tid == 0) {
#pragma unroll
        for (int i = 0; i < RING; i++) {
            mbar_init(mb_full[i], 1);
            mbar_init(mb_empty[i], 8);   // one arrive per warp
        }
        FENCE_ASYNC();
    }
    if (tid < TM) {
        int n = r0 + tid;
        float s = 0.0f;
        if (n < N) {
            int b = get_seg(seg, n);
            s = g_a[n] / (g_anorm[b] + 1e-8f) * g_ev[b];
        }
        s_sv[tid] = s;
    }
    s_wv[tid] = Wv[tid];
    __syncthreads();

    if (tid == 0) {
#pragma unroll
        for (int i = 0; i < RING; i++) {
            mbar_expect(mb_full[i], SCHUNK);
            bulk_g2s(wb_addr[i], g_Wf + (size_t)i * SCHUNK, SCHUNK, mb_full[i]);
        }
    }

    float Cm[2][8][4];   // accumulator / current activation tile
    float hR[2][8][4];   // residual h (register-resident)

    // ---- init: h0 = s (x) Wv into Cm; hR = Cm; store A = f16(silu(h0)).
    {
#pragma unroll
        for (int a = 0; a < 2; a++) {
            int rlo = 16 * (2 * m + a) + gid;
            float s0 = s_sv[rlo];
            float s1 = s_sv[rlo + 8];
#pragma unroll
            for (int jj = 0; jj < 8; jj++) {
                int col = 8 * (8 * nh + jj) + c2v;
                float w0 = s_wv[col], w1 = s_wv[col + 1];
                Cm[a][jj][0] = s0 * w0;
                Cm[a][jj][1] = s0 * w1;
                Cm[a][jj][2] = s1 * w0;
                Cm[a][jj][3] = s1 * w1;
                hR[a][jj][0] = Cm[a][jj][0];
                hR[a][jj][1] = Cm[a][jj][1];
                hR[a][jj][2] = Cm[a][jj][2];
                hR[a][jj][3] = Cm[a][jj][3];
            }
        }
        store_A_frags(Cm, aH, m, nh, l);
    }
    __syncthreads();

#pragma unroll 1
    for (int g = 0; g < 5; g++) {
        // ---- accumulator init: residual GEMMs start from h
        if (g == 1 || g == 3) {
#pragma unroll
            for (int a = 0; a < 2; a++)
#pragma unroll
                for (int jj = 0; jj < 8; jj++) {
                    Cm[a][jj][0] = hR[a][jj][0];
                    Cm[a][jj][1] = hR[a][jj][1];
                    Cm[a][jj][2] = hR[a][jj][2];
                    Cm[a][jj][3] = hR[a][jj][3];
                }
        } else {
#pragma unroll
            for (int a = 0; a < 2; a++)
#pragma unroll
                for (int jj = 0; jj < 8; jj++)
                    Cm[a][jj][0] = Cm[a][jj][1] = Cm[a][jj][2] = Cm[a][jj][3] = 0.0f;
        }

        // ---- mainloop: 2 superchunks of 4 k-chunks
#pragma unroll 1
        for (int sc = 0; sc < 2; sc++) {
            int q = 2 * g + sc;
            int s = q & (RING - 1);
            mbar_wait(mb_full[s], (uint32_t)((q >> 1) & 1));

#pragma unroll
            for (int ck = 0; ck < 4; ck++) {
                int c = sc * 4 + ck;   // global k-chunk in GEMM (0..7)
                const unsigned char* wt =
                    wb_ptr[s] + (size_t)ck * KCH + (size_t)l * 8 + nh * 2048;
#pragma unroll
                for (int t = 0; t < 2; t++) {
                    int slot0 = (2 * m + 0) * 16 + 2 * c + t;
                    int slot1 = (2 * m + 1) * 16 + 2 * c + t;
                    uint4 ah0 = *(const uint4*)(aH + (size_t)(slot0 * 32 + l) * 16);
                    uint4 ah1 = *(const uint4*)(aH + (size_t)(slot1 * 32 + l) * 16);
                    const unsigned char* wtt = wt + t * 8192;
#pragma unroll
                    for (int jj = 0; jj < 8; jj++) {
                        uint2 bh = *(const uint2*)(wtt + jj * 256);
                        mma_f32(Cm[0][jj], ah0, bh);
                        mma_f32(Cm[1][jj], ah1, bh);
                    }
                }
            }
            if (l == 0) mbar_arrive(mb_empty[s]);
            if (tid == 0 && q + RING < NSUPER) {
                int qq = q + RING;
                int fs = qq & (RING - 1);
                mbar_wait(mb_empty[fs], (uint32_t)(((qq >> 1) + 1) & 1));
                mbar_expect(mb_full[fs], SCHUNK);
                bulk_g2s(wb_addr[fs], g_Wf + (size_t)qq * SCHUNK, SCHUNK,
                         mb_full[fs]);
            }
        }

        __syncthreads();   // all warps done reading A

        // ---- epilogue
        if (g == 4) {
#pragma unroll
            for (int a = 0; a < 2; a++) {
                int rlo = r0 + 16 * (2 * m + a) + gid;
#pragma unroll
                for (int jj = 0; jj < 8; jj++) {
                    int col = 8 * (8 * nh + jj) + c2v;
                    if (rlo < N)
                        *(float2*)(out + (size_t)rlo * FDIM + col) =
                            make_float2(Cm[a][jj][0], Cm[a][jj][1]);
                    if (rlo + 8 < N)
                        *(float2*)(out + (size_t)(rlo + 8) * FDIM + col) =
                            make_float2(Cm[a][jj][2], Cm[a][jj][3]);
                }
            }
        } else {
            if (g == 1 || g == 3) {   // h updated: hR = Cm
#pragma unroll
                for (int a = 0; a < 2; a++)
#pragma unroll
                    for (int jj = 0; jj < 8; jj++) {
                        hR[a][jj][0] = Cm[a][jj][0];
                        hR[a][jj][1] = Cm[a][jj][1];
                        hR[a][jj][2] = Cm[a][jj][2];
                        hR[a][jj][3] = Cm[a][jj][3];
                    }
            }
            store_A_frags(Cm, aH, m, nh, l);
            __syncthreads();   // publish A before next GEMM reads
        }
    }
}

// ---------------------------------------------------------------------------
extern "C" void kernel_launch(void* const* d_in, const int* in_sizes, int n_in,
                              void* d_out, int out_size) {
    int base = (n_in >= 11 && in_sizes[2] == 1) ? 1 : 0;

    const float* x     = (const float*)d_in[0];
    const float* E     = (const float*)d_in[1];
    const void*  seg   = d_in[2 + base];
    const float* Wq    = (const float*)d_in[3 + base];
    const float* bq    = (const float*)d_in[4 + base];
    const float* Wk    = (const float*)d_in[5 + base];
    const float* Wv    = (const float*)d_in[6 + base];
    const float* Wres1 = (const float*)d_in[7 + base];
    const float* Wres2 = (const float*)d_in[8 + base];
    const float* Wout  = (const float*)d_in[9 + base];

    int N = in_sizes[0] / FDIM;
    int B = in_sizes[1];
    if (N > MAXN) N = MAXN;
    if (B > MAXB) B = MAXB;

    detect_kernel<<<1, 1>>>((const int*)seg, N);
    prep_kernel<<<1 + (B + 255) / 256, 256>>>(Wq, Wk, bq, E, B);
    convW_kernel<<<(CONVW_THREADS + 127) / 128, 128>>>(Wres1, Wres2, Wout);
    dot_kernel<<<(N + 63) / 64, 256>>>(x, seg, N);

    int smem_bytes = 32768 + RING * SCHUNK;   // 160 KB
    cudaFuncSetAttribute(chain_mma, cudaFuncAttributeMaxDynamicSharedMemorySize,
                         smem_bytes);
    chain_mma<<<(N + TM - 1) / TM, 256, smem_bytes>>>(seg, Wv, (float*)d_out, N);
}

// round 17
// speedup vs baseline: 1.8827x; 1.0033x over previous
#include <cuda_runtime.h>
#include <cuda_fp16.h>
#include <math.h>
#include <stdint.h>

// ===========================================================================
// ElectronicEmbedding (SpookyNet) — R17: R16 + A-tile double buffer (single
// sync per GEMM boundary) + detect merged into prep (4 launches; also shifts
// the ncu capture slot onto chain_mma for diagnostics).
// Pure fp16 HMMA chain, TM=64, 64KB W superchunks, RING=2, h in registers.
// ===========================================================================

#define FDIM 256
#define TM   64
#define MAXN 200704
#define MAXB 4096
#define KCH  16384            // one k-chunk W image (2 ktiles x 32 ntiles)
#define SCHUNK (4 * KCH)      // 64KB superchunk = 4 k-chunks
#define NSUPER 10             // 5 GEMMs x 2 superchunks
#define RING 2

__device__ __align__(16) unsigned char g_Wf[5 * 8 * KCH];

__device__ float g_u[FDIM];
__device__ float g_c0;
__device__ float g_cf[MAXB];
__device__ float g_ev[MAXB];
__device__ float g_anorm[MAXB];
__device__ float g_a[MAXN];
__device__ int   g_seg64;

// ---------------------------------------------------------------------------
__device__ __forceinline__ uint32_t smem_u32(const void* p) {
    uint32_t a;
    asm("{ .reg .u64 t; cvta.to.shared.u64 t, %1; cvt.u32.u64 %0, t; }"
        : "=r"(a) : "l"(p));
    return a;
}

__device__ __forceinline__ int get_seg(const void* seg, int n) {
    int b;
    if (g_seg64) b = (int)((const long long*)seg)[n];
    else         b = ((const int*)seg)[n];
    if (b < 0) b = 0;
    if (b >= MAXB) b = MAXB - 1;
    return b;
}

__device__ __forceinline__ float siluf(float x) {
    return x * (1.0f / (1.0f + __expf(-x)));
}

__device__ __forceinline__ uint32_t f16pack2(float a, float b) {
    __half2 h = __floats2half2_rn(a, b);
    return *(uint32_t*)&h;
}

// ---------------------------------------------------------------------------
// mbarrier / bulk copy
// ---------------------------------------------------------------------------
__device__ __forceinline__ void mbar_init(uint32_t m, uint32_t cnt) {
    asm volatile("mbarrier.init.shared.b64 [%0], %1;" :: "r"(m), "r"(cnt) : "memory");
}
__device__ __forceinline__ void mbar_expect(uint32_t m, uint32_t bytes) {
    asm volatile("mbarrier.arrive.expect_tx.shared.b64 _, [%0], %1;"
                 :: "r"(m), "r"(bytes) : "memory");
}
__device__ __forceinline__ void mbar_arrive(uint32_t m) {
    asm volatile("mbarrier.arrive.shared.b64 _, [%0];" :: "r"(m) : "memory");
}
__device__ __forceinline__ void mbar_wait(uint32_t m, uint32_t parity) {
    uint32_t done;
    asm volatile(
        "{\n\t.reg .pred p;\n\t"
        "mbarrier.try_wait.parity.acquire.cta.shared::cta.b64 p, [%1], %2;\n\t"
        "selp.b32 %0, 1, 0, p;\n\t}"
        : "=r"(done) : "r"(m), "r"(parity) : "memory");
    while (!done) {
        asm volatile(
            "{\n\t.reg .pred p;\n\t"
            "mbarrier.try_wait.parity.acquire.cta.shared::cta.b64 p, [%1], %2, 0x989680;\n\t"
            "selp.b32 %0, 1, 0, p;\n\t}"
            : "=r"(done) : "r"(m), "r"(parity) : "memory");
    }
}
__device__ __forceinline__ void bulk_g2s(uint32_t dst, const void* src,
                                         uint32_t bytes, uint32_t mbar) {
    asm volatile(
        "cp.async.bulk.shared::cluster.global.mbarrier::complete_tx::bytes "
        "[%0], [%1], %2, [%3];"
        :: "r"(dst), "l"(src), "r"(bytes), "r"(mbar) : "memory");
}
#define FENCE_ASYNC() asm volatile("fence.proxy.async.shared::cta;" ::: "memory")

// fp16 MMA, f32 accumulate
__device__ __forceinline__ void mma_f32(float c[4], uint4 a, uint2 b) {
    asm volatile(
        "mma.sync.aligned.m16n8k16.row.col.f32.f16.f16.f32 "
        "{%0,%1,%2,%3}, {%4,%5,%6,%7}, {%8,%9}, {%0,%1,%2,%3};"
        : "+f"(c[0]), "+f"(c[1]), "+f"(c[2]), "+f"(c[3])
        : "r"(a.x), "r"(a.y), "r"(a.z), "r"(a.w), "r"(b.x), "r"(b.y));
}

// ---------------------------------------------------------------------------
// prep (+seg-dtype detect merged in, so the launch sequence is 4 kernels)
// ---------------------------------------------------------------------------
__global__ void prep_kernel(const float* __restrict__ Wq,
                            const float* __restrict__ Wk,
                            const float* __restrict__ bq,
                            const float* __restrict__ E,
                            const int* __restrict__ seg32, int N, int B) {
    int tid = threadIdx.x;
    if (blockIdx.x == 0) {
        float s = 0.0f;
#pragma unroll 8
        for (int f = 0; f < FDIM; f++)
            s = fmaf(Wk[f], Wq[f * FDIM + tid], s);
        g_u[tid] = s;
        if (tid == 0) {
            float c = 0.0f;
            for (int f = 0; f < FDIM; f++) c = fmaf(bq[f], Wk[f], c);
            g_c0 = c;
        }
        if (tid == 1) {
            // seg dtype detect: int64 LE -> word N-1 is a high word == 0
            int last = seg32[N - 1];
            int prev = seg32[N - 2];
            g_seg64 = (last == 0 && prev > 0) ? 1 : 0;
        }
    } else {
        int b = (blockIdx.x - 1) * 256 + tid;
        if (b < B) {
            float e = fabsf(E[b]);
            g_ev[b] = e;
            g_cf[b] = e / fmaxf(e, 1.0f);
            g_anorm[b] = 0.0f;
        }
    }
}

// ---------------------------------------------------------------------------
// dot: 8 rows per warp, front-batched loads (MLP 16).
// ---------------------------------------------------------------------------
__global__ void dot_kernel(const float* __restrict__ x,
                           const void* __restrict__ seg, int N) {
    __shared__ float su[FDIM];
    __shared__ float sc0;
    int tid = threadIdx.x;
    su[tid] = g_u[tid];
    if (tid == 0) sc0 = g_c0;
    __syncthreads();

    int wid = tid >> 5, lane = tid & 31;
    int n0 = (blockIdx.x * 8 + wid) * 8;
    if (n0 >= N) return;

    float4 u0 = *(const float4*)&su[4 * lane];
    float4 u1 = *(const float4*)&su[128 + 4 * lane];

    float p[8];
#pragma unroll
    for (int r = 0; r < 8; r++) {
        int n = n0 + r;
        p[r] = 0.0f;
        if (n < N) {
            const float4* xr = (const float4*)(x + (size_t)n * FDIM);
            float4 xa = xr[lane];
            float4 xb = xr[32 + lane];
            p[r] = xa.x * u0.x + xa.y * u0.y + xa.z * u0.z + xa.w * u0.w +
                   xb.x * u1.x + xb.y * u1.y + xb.z * u1.z + xb.w * u1.w;
        }
    }
#pragma unroll
    for (int r = 0; r < 8; r++)
#pragma unroll
        for (int o = 16; o > 0; o >>= 1)
            p[r] += __shfl_down_sync(0xffffffffu, p[r], o);

    if (lane == 0) {
#pragma unroll
        for (int r = 0; r < 8; r++) {
            int n = n0 + r;
            if (n < N) {
                int b = get_seg(seg, n);
                float d = (p[r] + sc0) * g_cf[b] * 0.0625f;
                float a = fmaxf(d, 0.0f) + log1pf(expf(-fabsf(d)));
                g_a[n] = a;
                atomicAdd(&g_anorm[b], a);
            }
        }
    }
}

// ---------------------------------------------------------------------------
// convW: fp32 W[out][in] -> fragment-ordered fp16 chunk images.
// chunk layout: [t2(2)][j(32)][l(32)][2 uint32] = 16KB; chunks: [m(5)][c(8)].
// ---------------------------------------------------------------------------
#define CONVW_THREADS (5 * 8 * 2 * 32 * 32)   // 81920

__global__ void convW_kernel(const float* __restrict__ Wres1,
                             const float* __restrict__ Wres2,
                             const float* __restrict__ Wout) {
    int idx = blockIdx.x * blockDim.x + threadIdx.x;
    if (idx >= CONVW_THREADS) return;
    int l  = idx & 31;
    int j  = (idx >> 5) & 31;
    int t2 = (idx >> 10) & 1;
    int c  = (idx >> 11) & 7;
    int m  = idx >> 14;
    if (m >= 5) return;

    const float* Wm;
    switch (m) {
        case 0: Wm = Wres1; break;
        case 1: Wm = Wres2; break;
        case 2: Wm = Wres1 + 65536; break;
        case 3: Wm = Wres2 + 65536; break;
        default: Wm = Wout; break;
    }
    int n  = 8 * j + (l >> 2);
    int k0 = 32 * c + 16 * t2 + (l & 3) * 2;
    const float* p = Wm + n * FDIM + k0;
    uint32_t H0 = f16pack2(p[0], p[1]);
    uint32_t H1 = f16pack2(p[8], p[9]);
    size_t base = (size_t)(m * 8 + c) * KCH +
                  (size_t)(((t2 * 32 + j) * 32 + l)) * 8;
    *(uint2*)(g_Wf + base) = make_uint2(H0, H1);
}

// ---------------------------------------------------------------------------
// Epilogue store helper: totals -> silu -> fp16 A frags.
// ---------------------------------------------------------------------------
__device__ __forceinline__ void store_A_frags(const float Cm[2][8][4],
                                              unsigned char* aBuf,
                                              int m, int nh, int l) {
#pragma unroll
    for (int a = 0; a < 2; a++) {
#pragma unroll
        for (int tt = 0; tt < 4; tt++) {
            const float* X = Cm[a][2 * tt];
            const float* Y = Cm[a][2 * tt + 1];
            uint32_t H0 = f16pack2(siluf(X[0]), siluf(X[1]));
            uint32_t H1 = f16pack2(siluf(X[2]), siluf(X[3]));
            uint32_t H2 = f16pack2(siluf(Y[0]), siluf(Y[1]));
            uint32_t H3 = f16pack2(siluf(Y[2]), siluf(Y[3]));
            int slot = (2 * m + a) * 16 + 4 * nh + tt;
            size_t ao = (size_t)(slot * 32 + l) * 16;
            *(uint4*)(aBuf + ao) = make_uint4(H0, H1, H2, H3);
        }
    }
}

// ---------------------------------------------------------------------------
// chain_mma: 64 rows/CTA, 256 threads (8 warps), 1 CTA/SM.
// A double-buffered: GEMM g reads aBuf[g&1], epilogue writes aBuf[(g+1)&1]
// -> single __syncthreads per GEMM boundary.
// SMEM: aH0 32K | aH1 32K | W ring 2 x 64K = 192K.
// ---------------------------------------------------------------------------
__global__ __launch_bounds__(256, 1)
void chain_mma(const void* __restrict__ seg,
               const float* __restrict__ Wv,
               float* __restrict__ out, int N) {
    extern __shared__ __align__(1024) unsigned char dyn[];
    unsigned char* aBuf[2] = { dyn, dyn + 32768 };
    uint32_t wb_addr[RING];
    unsigned char* wb_ptr[RING];
#pragma unroll
    for (int i = 0; i < RING; i++) {
        wb_ptr[i] = dyn + 65536 + i * SCHUNK;
        wb_addr[i] = smem_u32(wb_ptr[i]);
    }

    __shared__ __align__(8) unsigned long long s_mb[2 * RING];
    __shared__ float s_sv[TM];
    __shared__ float s_wv[FDIM];

    int tid = threadIdx.x;
    int w = tid >> 5, l = tid & 31;
    int m = w >> 2, nh = w & 3;
    int gid = l >> 2;
    int c2v = (l & 3) * 2;
    int r0 = blockIdx.x * TM;

    uint32_t mb_full[RING], mb_empty[RING];
#pragma unroll
    for (int i = 0; i < RING; i++) {
        mb_full[i]  = smem_u32(&s_mb[i]);
        mb_empty[i] = smem_u32(&s_mb[RING + i]);
    }

    if (tid == 0) {
#pragma unroll
        for (int i = 0; i < RING; i++) {
            mbar_init(mb_full[i], 1);
            mbar_init(mb_empty[i], 8);   // one arrive per warp
        }
        FENCE_ASYNC();
    }
    if (tid < TM) {
        int n = r0 + tid;
        float s = 0.0f;
        if (n < N) {
            int b = get_seg(seg, n);
            s = g_a[n] / (g_anorm[b] + 1e-8f) * g_ev[b];
        }
        s_sv[tid] = s;
    }
    s_wv[tid] = Wv[tid];
    __syncthreads();

    if (tid == 0) {
#pragma unroll
        for (int i = 0; i < RING; i++) {
            mbar_expect(mb_full[i], SCHUNK);
            bulk_g2s(wb_addr[i], g_Wf + (size_t)i * SCHUNK, SCHUNK, mb_full[i]);
        }
    }

    float Cm[2][8][4];   // accumulator / current activation tile
    float hR[2][8][4];   // residual h (register-resident)

    // ---- init: h0 = s (x) Wv into Cm; hR = Cm; A(buf0) = f16(silu(h0)).
    {
#pragma unroll
        for (int a = 0; a < 2; a++) {
            int rlo = 16 * (2 * m + a) + gid;
            float s0 = s_sv[rlo];
            float s1 = s_sv[rlo + 8];
#pragma unroll
            for (int jj = 0; jj < 8; jj++) {
                int col = 8 * (8 * nh + jj) + c2v;
                float w0 = s_wv[col], w1 = s_wv[col + 1];
                Cm[a][jj][0] = s0 * w0;
                Cm[a][jj][1] = s0 * w1;
                Cm[a][jj][2] = s1 * w0;
                Cm[a][jj][3] = s1 * w1;
                hR[a][jj][0] = Cm[a][jj][0];
                hR[a][jj][1] = Cm[a][jj][1];
                hR[a][jj][2] = Cm[a][jj][2];
                hR[a][jj][3] = Cm[a][jj][3];
            }
        }
        store_A_frags(Cm, aBuf[0], m, nh, l);
    }
    __syncthreads();

#pragma unroll 1
    for (int g = 0; g < 5; g++) {
        const unsigned char* aH = aBuf[g & 1];

        // ---- accumulator init: residual GEMMs start from h
        if (g == 1 || g == 3) {
#pragma unroll
            for (int a = 0; a < 2; a++)
#pragma unroll
                for (int jj = 0; jj < 8; jj++) {
                    Cm[a][jj][0] = hR[a][jj][0];
                    Cm[a][jj][1] = hR[a][jj][1];
                    Cm[a][jj][2] = hR[a][jj][2];
                    Cm[a][jj][3] = hR[a][jj][3];
                }
        } else {
#pragma unroll
            for (int a = 0; a < 2; a++)
#pragma unroll
                for (int jj = 0; jj < 8; jj++)
                    Cm[a][jj][0] = Cm[a][jj][1] = Cm[a][jj][2] = Cm[a][jj][3] = 0.0f;
        }

        // ---- mainloop: 2 superchunks of 4 k-chunks
#pragma unroll 1
        for (int sc = 0; sc < 2; sc++) {
            int q = 2 * g + sc;
            int s = q & (RING - 1);
            mbar_wait(mb_full[s], (uint32_t)((q >> 1) & 1));

#pragma unroll
            for (int ck = 0; ck < 4; ck++) {
                int c = sc * 4 + ck;   // global k-chunk in GEMM (0..7)
                const unsigned char* wt =
                    wb_ptr[s] + (size_t)ck * KCH + (size_t)l * 8 + nh * 2048;
#pragma unroll
                for (int t = 0; t < 2; t++) {
                    int slot0 = (2 * m + 0) * 16 + 2 * c + t;
                    int slot1 = (2 * m + 1) * 16 + 2 * c + t;
                    uint4 ah0 = *(const uint4*)(aH + (size_t)(slot0 * 32 + l) * 16);
                    uint4 ah1 = *(const uint4*)(aH + (size_t)(slot1 * 32 + l) * 16);
                    const unsigned char* wtt = wt + t * 8192;
#pragma unroll
                    for (int jj = 0; jj < 8; jj++) {
                        uint2 bh = *(const uint2*)(wtt + jj * 256);
                        mma_f32(Cm[0][jj], ah0, bh);
                        mma_f32(Cm[1][jj], ah1, bh);
                    }
                }
            }
            if (l == 0) mbar_arrive(mb_empty[s]);
            if (tid == 0 && q + RING < NSUPER) {
                int qq = q + RING;
                int fs = qq & (RING - 1);
                mbar_wait(mb_empty[fs], (uint32_t)(((qq >> 1) + 1) & 1));
                mbar_expect(mb_full[fs], SCHUNK);
                bulk_g2s(wb_addr[fs], g_Wf + (size_t)qq * SCHUNK, SCHUNK,
                         mb_full[fs]);
            }
        }

        // ---- epilogue (writes the OTHER A buffer -> no drain sync needed)
        if (g == 4) {
#pragma unroll
            for (int a = 0; a < 2; a++) {
                int rlo = r0 + 16 * (2 * m + a) + gid;
#pragma unroll
                for (int jj = 0; jj < 8; jj++) {
                    int col = 8 * (8 * nh + jj) + c2v;
                    if (rlo < N)
                        *(float2*)(out + (size_t)rlo * FDIM + col) =
                            make_float2(Cm[a][jj][0], Cm[a][jj][1]);
                    if (rlo + 8 < N)
                        *(float2*)(out + (size_t)(rlo + 8) * FDIM + col) =
                            make_float2(Cm[a][jj][2], Cm[a][jj][3]);
                }
            }
        } else {
            if (g == 1 || g == 3) {   // h updated: hR = Cm
#pragma unroll
                for (int a = 0; a < 2; a++)
#pragma unroll
                    for (int jj = 0; jj < 8; jj++) {
                        hR[a][jj][0] = Cm[a][jj][0];
                        hR[a][jj][1] = Cm[a][jj][1];
                        hR[a][jj][2] = Cm[a][jj][2];
                        hR[a][jj][3] = Cm[a][jj][3];
                    }
            }
            store_A_frags(Cm, aBuf[(g + 1) & 1], m, nh, l);
            __syncthreads();   // publish A for next GEMM (single sync)
        }
    }
}

// ---------------------------------------------------------------------------
extern "C" void kernel_launch(void* const* d_in, const int* in_sizes, int n_in,
                              void* d_out, int out_size) {
    int base = (n_in >= 11 && in_sizes[2] == 1) ? 1 : 0;

    const float* x     = (const float*)d_in[0];
    const float* E     = (const float*)d_in[1];
    const void*  seg   = d_in[2 + base];
    const float* Wq    = (const float*)d_in[3 + base];
    const float* bq    = (const float*)d_in[4 + base];
    const float* Wk    = (const float*)d_in[5 + base];
    const float* Wv    = (const float*)d_in[6 + base];
    const float* Wres1 = (const float*)d_in[7 + base];
    const float* Wres2 = (const float*)d_in[8 + base];
    const float* Wout  = (const float*)d_in[9 + base];

    int N = in_sizes[0] / FDIM;
    int B = in_sizes[1];
    if (N > MAXN) N = MAXN;
    if (B > MAXB) B = MAXB;

    prep_kernel<<<1 + (B + 255) / 256, 256>>>(Wq, Wk, bq, E,
                                              (const int*)seg, N, B);
    convW_kernel<<<(CONVW_THREADS + 127) / 128, 128>>>(Wres1, Wres2, Wout);
    dot_kernel<<<(N + 63) / 64, 256>>>(x, seg, N);

    int smem_bytes = 65536 + RING * SCHUNK;   // 192 KB
    cudaFuncSetAttribute(chain_mma, cudaFuncAttributeMaxDynamicSharedMemorySize,
                         smem_bytes);
    chain_mma<<<(N + TM - 1) / TM, 256, smem_bytes>>>(seg, Wv, (float*)d_out, N);
}